// round 8
// baseline (speedup 1.0000x reference)
#include <cuda_runtime.h>

static constexpr int KC = 5;
static constexpr int DC = 10;
static constexpr int NBINS = 16384;
static constexpr float EPS_MARGIN = 1e-4f;

__device__ unsigned char g_lut[NBINS];

// strict < keeps first occurrence (matches jnp.argmin); scores = {0, g1..g4}
__device__ __forceinline__ float select_idx(float g1, float g2, float g3, float g4) {
    float best = 0.0f, idx = 0.0f;
    idx  = (g1 < best) ? 1.0f : idx;  best = fminf(g1, best);
    idx  = (g2 < best) ? 2.0f : idx;  best = fminf(g2, best);
    idx  = (g3 < best) ? 3.0f : idx;  best = fminf(g3, best);
    idx  = (g4 < best) ? 4.0f : idx;  best = fminf(g4, best);
    return idx;
}

// ---------------- Kernel A: LUT builder ----------------
__global__ __launch_bounds__(256) void vq_build_lut(const float* __restrict__ emb)
{
    int bin = blockIdx.x * blockDim.x + threadIdx.x;
    if (bin >= NBINS) return;

    // Difference-poly coefficients vs code 0 (EXACT same expressions as fallback)
    float c[KC - 1][DC], d[KC - 1];
    {
        float e0[DC], s0 = 0.0f;
        #pragma unroll
        for (int i = 0; i < DC; i++) { e0[i] = emb[i]; s0 = fmaf(e0[i], e0[i], s0); }
        #pragma unroll
        for (int k = 1; k < KC; k++) {
            float sk = 0.0f;
            #pragma unroll
            for (int i = 0; i < DC; i++) {
                float e = emb[k * DC + i];
                sk = fmaf(e, e, sk);
                c[k - 1][i] = -2.0f * (e - e0[i]);
            }
            d[k - 1] = sk - s0;
        }
    }

    const float offs[7] = {-0.25f, 0.0f, 0.25f, 0.5f, 0.75f, 1.0f, 1.25f};
    int w0 = -1;
    bool ok = true;
    #pragma unroll
    for (int t = 0; t < 7; t++) {
        float v = ((float)bin + offs[t]) * (1.0f / (float)NBINS);
        float sc[KC];
        sc[0] = 0.0f;
        #pragma unroll
        for (int k = 0; k < KC - 1; k++) {
            float h = c[k][DC - 1];
            #pragma unroll
            for (int j = DC - 2; j >= 0; j--) h = fmaf(h, v, c[k][j]);
            sc[k + 1] = fmaf(h, v, d[k]);
        }
        int w = 0; float best = sc[0];
        #pragma unroll
        for (int k = 1; k < KC; k++) if (sc[k] < best) { best = sc[k]; w = k; }
        float second = 3.4e38f;
        #pragma unroll
        for (int k = 0; k < KC; k++) if (k != w) second = fminf(second, sc[k]);
        if (t == 0) w0 = w;
        ok = ok && (w == w0) && (second - best > EPS_MARGIN);
    }
    // Edge bins always sentinel: out-of-range values clamp here and must take
    // the exact fallback path.
    if (bin == 0 || bin == NBINS - 1) ok = false;
    g_lut[bin] = ok ? (unsigned char)w0 : (unsigned char)255;
}

// ---------------- Kernel B: LUT-mapped quantize ----------------
__global__ __launch_bounds__(256) void vq_map(
    const float* __restrict__ x, const float* __restrict__ emb,
    float* __restrict__ out, int n)
{
    __shared__ unsigned char slut[NBINS];
    __shared__ float scoef[(KC - 1) * DC + (KC - 1)];

    {
        const uint4* src = (const uint4*)g_lut;
        uint4* dst = (uint4*)slut;
        #pragma unroll
        for (int i = threadIdx.x; i < NBINS / 16; i += 256) dst[i] = src[i];
    }
    if (threadIdx.x < (KC - 1) * DC) {
        int k = threadIdx.x / DC + 1, j = threadIdx.x % DC;
        scoef[threadIdx.x] = -2.0f * (emb[k * DC + j] - emb[j]);
    } else if (threadIdx.x < (KC - 1) * DC + (KC - 1)) {
        int k = threadIdx.x - (KC - 1) * DC + 1;
        float sk = 0.0f, s0 = 0.0f;
        #pragma unroll
        for (int i = 0; i < DC; i++) {
            float ek = emb[k * DC + i], e0 = emb[i];
            sk = fmaf(ek, ek, sk);
            s0 = fmaf(e0, e0, s0);
        }
        scoef[threadIdx.x] = sk - s0;
    }
    __syncthreads();

    auto fallback = [&](float v) -> float {
        float g[KC - 1];
        #pragma unroll
        for (int k = 0; k < KC - 1; k++) {
            float h = scoef[k * DC + DC - 1];
            #pragma unroll
            for (int j = DC - 2; j >= 0; j--) h = fmaf(h, v, scoef[k * DC + j]);
            g[k] = fmaf(h, v, scoef[(KC - 1) * DC + k]);
        }
        return select_idx(g[0], g[1], g[2], g[3]);
    };

    // Fast lookup: clamp (IMNMX), LDS.u8, I2F. Sentinel (255) => exact path.
    auto lookup = [&](float v) -> unsigned {
        int b = (int)(v * (float)NBINS);       // trunc toward zero
        b = max(b, 0);
        b = min(b, NBINS - 1);
        return (unsigned)slut[b];
    };

    const int n4 = n >> 2;
    const float4* __restrict__ x4 = (const float4*)x;
    float4* __restrict__ o4 = (float4*)out;
    const int stride = gridDim.x * blockDim.x;
    const int tid0 = blockIdx.x * blockDim.x + threadIdx.x;

    // Unroll-2: 8 elements per iteration, both LDG.128 front-batched.
    for (int i = tid0; i < n4; i += 2 * stride) {
        int i2 = i + stride;
        bool v2ok = (i2 < n4);
        float4 a = x4[i];
        float4 b;
        if (v2ok) b = x4[i2];

        float va[8] = {a.x, a.y, a.z, a.w,
                       v2ok ? b.x : 0.5f, v2ok ? b.y : 0.5f,
                       v2ok ? b.z : 0.5f, v2ok ? b.w : 0.5f};
        unsigned code[8];
        unsigned ormask = 0;
        #pragma unroll
        for (int e = 0; e < 8; e++) {
            code[e] = lookup(va[e]);
            ormask |= code[e];
        }
        float res[8];
        #pragma unroll
        for (int e = 0; e < 8; e++) res[e] = (float)code[e];
        if (ormask & 0x80u) {                   // some sentinel: exact poly path
            #pragma unroll
            for (int e = 0; e < 8; e++)
                if (code[e] == 255u) res[e] = fallback(va[e]);
        }
        o4[i] = make_float4(res[0], res[1], res[2], res[3]);
        if (v2ok) o4[i2] = make_float4(res[4], res[5], res[6], res[7]);
    }

    // Scalar tail (n % 4): exact fallback.
    for (int t = (n4 << 2) + tid0; t < n; t += stride)
        out[t] = fallback(x[t]);
}

extern "C" void kernel_launch(void* const* d_in, const int* in_sizes, int n_in,
                              void* d_out, int out_size)
{
    const float* x   = (const float*)d_in[0];
    const float* emb = (const float*)d_in[1];
    if (n_in >= 2 && in_sizes[0] == KC * DC && in_sizes[1] != KC * DC) {
        x   = (const float*)d_in[1];
        emb = (const float*)d_in[0];
    }
    float* out = (float*)d_out;
    int n = out_size;

    vq_build_lut<<<NBINS / 256, 256>>>(emb);
    vq_map<<<592, 256>>>(x, emb, out, n);   // 4 CTAs/SM, 16KB smem each
}

// round 9
// speedup vs baseline: 1.1043x; 1.1043x over previous
#include <cuda_runtime.h>

static constexpr int KC = 5;
static constexpr int DC = 10;
static constexpr int NBINS = 16384;
static constexpr int MAXJ = 24;
static constexpr float EPS_MARGIN = 1e-4f;

__device__ float g_t[MAXJ];   // transition thresholds (unsorted)
__device__ float g_d[MAXJ];   // state deltas at each transition
__device__ int   g_cnt;

// ---------------- Kernel 0: reset + pad (graph-replay safe) ----------------
__global__ void vq_reset() {
    int i = threadIdx.x;
    if (i < MAXJ) { g_t[i] = 1e30f; g_d[i] = 0.0f; }  // padded entries are no-ops
    if (i == 0) g_cnt = 0;
}

// ---------------- Kernel 1: builder — emit step-function transitions ----------------
__global__ __launch_bounds__(256) void vq_build(const float* __restrict__ emb)
{
    int bin = blockIdx.x * blockDim.x + threadIdx.x;
    if (bin >= NBINS) return;

    // Difference-poly coefficients vs code 0 (same expressions as fallback)
    float c[KC - 1][DC], d[KC - 1];
    {
        float e0[DC], s0 = 0.0f;
        #pragma unroll
        for (int i = 0; i < DC; i++) { e0[i] = emb[i]; s0 = fmaf(e0[i], e0[i], s0); }
        #pragma unroll
        for (int k = 1; k < KC; k++) {
            float sk = 0.0f;
            #pragma unroll
            for (int i = 0; i < DC; i++) {
                float e = emb[k * DC + i];
                sk = fmaf(e, e, sk);
                c[k - 1][i] = -2.0f * (e - e0[i]);
            }
            d[k - 1] = sk - s0;
        }
    }

    // 11 samples spanning [bin-1.25, bin+1.25] bins in 0.25 steps:
    // prev-bin state uses m=0..6, this-bin state uses m=4..10 (same dilated
    // 7-point validation as the proven LUT builder).
    int win[11]; bool okm[11];
    #pragma unroll
    for (int m = 0; m < 11; m++) {
        float v = ((float)bin + 0.25f * (float)(m - 5)) * (1.0f / (float)NBINS);
        float sc[KC];
        sc[0] = 0.0f;
        #pragma unroll
        for (int k = 0; k < KC - 1; k++) {
            float h = c[k][DC - 1];
            #pragma unroll
            for (int j = DC - 2; j >= 0; j--) h = fmaf(h, v, c[k][j]);
            sc[k + 1] = fmaf(h, v, d[k]);
        }
        int w = 0; float best = sc[0];
        #pragma unroll
        for (int k = 1; k < KC; k++) if (sc[k] < best) { best = sc[k]; w = k; }
        float second = 3.4e38f;
        #pragma unroll
        for (int k = 0; k < KC; k++) if (k != w) second = fminf(second, sc[k]);
        win[m] = w;
        okm[m] = (second - best) > EPS_MARGIN;
    }

    auto state7 = [&](int s) -> int {
        int w = win[s];
        bool good = true;
        #pragma unroll
        for (int t = 0; t < 7; t++) good = good && (win[s + t] == w) && okm[s + t];
        return good ? w : 255;
    };

    // Edge bins forced sentinel (covers v near 0 and v in last bin / >= 1).
    int st_prev = (bin <= 1) ? 255 : state7(0);                    // state(bin-1)
    int st_cur  = (bin == 0 || bin == NBINS - 1) ? 255 : state7(4); // state(bin)

    if (st_cur != st_prev) {
        int idx = atomicAdd(&g_cnt, 1);
        if (idx < MAXJ) {
            g_t[idx] = (float)bin * (1.0f / (float)NBINS);  // exact
            g_d[idx] = (float)(st_cur - st_prev);           // exact small int
        }
    }
}

// ---------------- exact polynomial fallback (identical math to rounds 6/8) ----------------
__device__ __forceinline__ float vq_fallback(float v, const float* scoef) {
    float g[KC - 1];
    #pragma unroll
    for (int k = 0; k < KC - 1; k++) {
        float h = scoef[k * DC + DC - 1];
        #pragma unroll
        for (int j = DC - 2; j >= 0; j--) h = fmaf(h, v, scoef[k * DC + j]);
        g[k] = fmaf(h, v, scoef[(KC - 1) * DC + k]);
    }
    float best = 0.0f, idx = 0.0f;
    idx = (g[0] < best) ? 1.0f : idx;  best = fminf(g[0], best);
    idx = (g[1] < best) ? 2.0f : idx;  best = fminf(g[1], best);
    idx = (g[2] < best) ? 3.0f : idx;  best = fminf(g[2], best);
    idx = (g[3] < best) ? 4.0f : idx;  best = fminf(g[3], best);
    return idx;
}

template<int T>
__device__ __forceinline__ void map_loop(const float4* __restrict__ x4,
                                         float4* __restrict__ o4, int n4,
                                         const float* scoef, int tid0, int stride)
{
    float tt[T], dd[T];
    #pragma unroll
    for (int j = 0; j < T; j++) { tt[j] = g_t[j]; dd[j] = g_d[j]; }

    for (int i = tid0; i < n4; i += stride) {
        float4 a = x4[i];
        float r0 = 255.0f, r1 = 255.0f, r2 = 255.0f, r3 = 255.0f;
        #pragma unroll
        for (int j = 0; j < T; j++) {
            if (a.x >= tt[j]) r0 += dd[j];
            if (a.y >= tt[j]) r1 += dd[j];
            if (a.z >= tt[j]) r2 += dd[j];
            if (a.w >= tt[j]) r3 += dd[j];
        }
        if (fmaxf(fmaxf(r0, r1), fmaxf(r2, r3)) > 4.5f) {  // rare sentinel gap
            if (r0 > 4.5f) r0 = vq_fallback(a.x, scoef);
            if (r1 > 4.5f) r1 = vq_fallback(a.y, scoef);
            if (r2 > 4.5f) r2 = vq_fallback(a.z, scoef);
            if (r3 > 4.5f) r3 = vq_fallback(a.w, scoef);
        }
        o4[i] = make_float4(r0, r1, r2, r3);
    }
}

// Cold paths out-of-line so they don't inflate the hot path's registers.
__device__ __noinline__ void map_loop_24(const float4* x4, float4* o4, int n4,
                                         const float* scoef, int tid0, int stride)
{
    map_loop<MAXJ>(x4, o4, n4, scoef, tid0, stride);
}
__device__ __noinline__ void map_all_poly(const float4* x4, float4* o4, int n4,
                                          const float* scoef, int tid0, int stride)
{
    for (int i = tid0; i < n4; i += stride) {
        float4 a = x4[i];
        float4 r;
        r.x = vq_fallback(a.x, scoef);
        r.y = vq_fallback(a.y, scoef);
        r.z = vq_fallback(a.z, scoef);
        r.w = vq_fallback(a.w, scoef);
        o4[i] = r;
    }
}

// ---------------- Kernel 2: map ----------------
__global__ __launch_bounds__(256) void vq_map(
    const float* __restrict__ x, const float* __restrict__ emb,
    float* __restrict__ out, int n)
{
    __shared__ float scoef[(KC - 1) * DC + (KC - 1)];
    if (threadIdx.x < (KC - 1) * DC) {
        int k = threadIdx.x / DC + 1, j = threadIdx.x % DC;
        scoef[threadIdx.x] = -2.0f * (emb[k * DC + j] - emb[j]);
    } else if (threadIdx.x < (KC - 1) * DC + (KC - 1)) {
        int k = threadIdx.x - (KC - 1) * DC + 1;
        float sk = 0.0f, s0 = 0.0f;
        #pragma unroll
        for (int i = 0; i < DC; i++) {
            float ek = emb[k * DC + i], e0 = emb[i];
            sk = fmaf(ek, ek, sk);
            s0 = fmaf(e0, e0, s0);
        }
        scoef[threadIdx.x] = sk - s0;
    }
    __syncthreads();

    const int n4 = n >> 2;
    const float4* __restrict__ x4 = (const float4*)x;
    float4* __restrict__ o4 = (float4*)out;
    const int stride = gridDim.x * blockDim.x;
    const int tid0 = blockIdx.x * blockDim.x + threadIdx.x;

    int J = g_cnt;
    if (J <= 12)        map_loop<12>(x4, o4, n4, scoef, tid0, stride);
    else if (J <= MAXJ) map_loop_24(x4, o4, n4, scoef, tid0, stride);
    else                map_all_poly(x4, o4, n4, scoef, tid0, stride);

    // Scalar tail (n % 4): exact fallback.
    for (int t = (n4 << 2) + tid0; t < n; t += stride)
        out[t] = vq_fallback(x[t], scoef);
}

extern "C" void kernel_launch(void* const* d_in, const int* in_sizes, int n_in,
                              void* d_out, int out_size)
{
    const float* x   = (const float*)d_in[0];
    const float* emb = (const float*)d_in[1];
    if (n_in >= 2 && in_sizes[0] == KC * DC && in_sizes[1] != KC * DC) {
        x   = (const float*)d_in[1];
        emb = (const float*)d_in[0];
    }
    float* out = (float*)d_out;
    int n = out_size;

    vq_reset<<<1, 32>>>();
    vq_build<<<NBINS / 256, 256>>>(emb);
    vq_map<<<592, 256>>>(x, emb, out, n);
}